// round 2
// baseline (speedup 1.0000x reference)
#include <cuda_runtime.h>

// RiemannSolver: per-cell flux = select(label){MLP_ds, MLP_dr, MLP_rs, 0}, with
// HLLE override for near-continuous states and flip normalization.
//
// Strategy: 1 thread per cell. Weights for all 3 MLPs staged in shared memory
// (~19KB). Each thread runs ONLY its label's MLP (3x FLOP reduction vs dense),
// using packed fma.rn.f32x2 (FFMA2) over hidden-unit pairs (2x fp32 FMA rate),
// and a 2-MUFU tanh (EX2 + RCP).

typedef unsigned long long u64;

#define NTH 256
#define GAMMA_F 1.6666666666666667f
// per-MLP shared layout: W1[20*64]=1280 | b1[64] | W2 padded [64*4]=256 | b2[4]
#define MLP_STRIDE 1604
#define SH_TOTAL (3 * MLP_STRIDE)

__device__ __forceinline__ u64 pack2(float lo, float hi) {
    u64 r;
    asm("mov.b64 %0, {%1, %2};" : "=l"(r) : "f"(lo), "f"(hi));
    return r;
}
__device__ __forceinline__ void unpack2(u64 v, float& lo, float& hi) {
    asm("mov.b64 {%0, %1}, %2;" : "=f"(lo), "=f"(hi) : "l"(v));
}
__device__ __forceinline__ u64 fma2(u64 a, u64 b, u64 c) {
    u64 d;
    asm("fma.rn.f32x2 %0, %1, %2, %3;" : "=l"(d) : "l"(a), "l"(b), "l"(c));
    return d;
}

// tanh(x) = sign(x) * (1 - 2/(exp(2|x|)+1)); 2 MUFU ops, ~1e-6 rel err.
// exp overflow -> inf -> 2/inf = 0 -> 1 : correct saturation.
__device__ __forceinline__ float fast_tanh(float x) {
    float a = fabsf(x);
    float e = __expf(a + a);
    float r = 1.0f - __fdividef(2.0f, e + 1.0f);
    return copysignf(r, x);
}

__global__ __launch_bounds__(NTH)
void riemann_kernel(
    const float* __restrict__ P, const float* __restrict__ U,
    const float* __restrict__ F,
    const float* __restrict__ cmax, const float* __restrict__ cmin,
    const float* __restrict__ W1_0, const float* __restrict__ b1_0,
    const float* __restrict__ W2_0, const float* __restrict__ b2_0,
    const float* __restrict__ W1_1, const float* __restrict__ b1_1,
    const float* __restrict__ W2_1, const float* __restrict__ b2_1,
    const float* __restrict__ W1_2, const float* __restrict__ b1_2,
    const float* __restrict__ W2_2, const float* __restrict__ b2_2,
    float* __restrict__ out, int N)
{
    __shared__ float sh[SH_TOTAL];

    // Stage all 3 MLPs into shared. W2 rows padded from 3 to 4 floats so that
    // per-row float4 loads are 16B-aligned (1604*4 and 1344*4 are both %16==0).
    for (int idx = threadIdx.x; idx < SH_TOTAL; idx += NTH) {
        int m = idx / MLP_STRIDE;
        int r = idx - m * MLP_STRIDE;
        const float* W1 = (m == 0) ? W1_0 : (m == 1) ? W1_1 : W1_2;
        const float* b1 = (m == 0) ? b1_0 : (m == 1) ? b1_1 : b1_2;
        const float* W2 = (m == 0) ? W2_0 : (m == 1) ? W2_1 : W2_2;
        const float* b2 = (m == 0) ? b2_0 : (m == 1) ? b2_1 : b2_2;
        float v;
        if (r < 1280) {
            v = W1[r];
        } else if (r < 1344) {
            v = b1[r - 1280];
        } else if (r < 1600) {
            int t = r - 1344;
            int j = t >> 2, k = t & 3;
            v = (k < 3) ? W2[j * 3 + k] : 0.0f;
        } else {
            int k = r - 1600;
            v = (k < 3) ? b2[k] : 0.0f;
        }
        sh[idx] = v;
    }
    __syncthreads();

    int n = blockIdx.x * NTH + threadIdx.x;
    if (n >= N) return;

    // ---- load cell: (3 components) x (2 sides), contiguous 6 floats per cell
    const float2* Pp = reinterpret_cast<const float2*>(P) + (size_t)n * 3;
    const float2* Up = reinterpret_cast<const float2*>(U) + (size_t)n * 3;
    const float2* Fp = reinterpret_cast<const float2*>(F) + (size_t)n * 3;
    float2 P0 = Pp[0], P1 = Pp[1], P2 = Pp[2];
    float2 U0 = Up[0], U1 = Up[1], U2 = Up[2];
    float2 F0 = Fp[0], F1 = Fp[1], F2 = Fp[2];
    float cx = cmax[n];
    float cn = cmin[n];

    // ---- flip normalization: sgn = (1,1,-1) for P,U; (-1,-1,1) for F; sides swap
    bool flip = P1.y > P1.x;
    if (flip) {
        float t;
        t = P0.x; P0.x = P0.y; P0.y = t;
        t = P1.x; P1.x = P1.y; P1.y = t;
        t = P2.x; P2.x = -P2.y; P2.y = -t;
        t = U0.x; U0.x = U0.y; U0.y = t;
        t = U1.x; U1.x = U1.y; U1.y = t;
        t = U2.x; U2.x = -U2.y; U2.y = -t;
        t = F0.x; F0.x = -F0.y; F0.y = -t;
        t = F1.x; F1.x = -F1.y; F1.y = -t;
        t = F2.x; F2.x = F2.y;  F2.y = t;
    }

    // ---- near-continuous check (on flipped primitives)
    float d0 = fabsf(P0.y - P0.x);
    float d1 = fabsf(P1.y - P1.x);
    float d2 = fabsf(P2.y - P2.x);
    bool cont = fmaxf(d0, fmaxf(d1, d2)) < 0.005f;

    // ---- HLLE flux (uses unflipped cmax/cmin, flipped U/F)
    float inv = 1.0f / (cx - cn);
    float cc = cx * cn;
    float hl0 = (cx * F0.x - cn * F0.y + cc * (U0.y - U0.x)) * inv;
    float hl1 = (cx * F1.x - cn * F1.y + cc * (U1.y - U1.x)) * inv;
    float hl2 = (cx * F2.x - cn * F2.y + cc * (U2.y - U2.x)) * inv;

    // ---- wave-pattern classification
    float r0 = P0.x, r1 = P0.y;   // rho
    float q0 = P1.x, q1 = P1.y;   // p
    float v0 = P2.x, v1 = P2.y;   // v
    float c0 = sqrtf(GAMMA_F * q0 / r0);
    float c1 = sqrtf(GAMMA_F * q1 / r1);
    float dv = v1 - v0;
    // (gamma-1)/2 = 1/3 ; z = (gamma-1)/(2 gamma) = 0.2 ; 1/z = 5
    float num = c0 + c1 - 0.33333334f * dv;
    float pz0 = exp2f(0.2f * __log2f(q0));
    float pz1 = exp2f(0.2f * __log2f(q1));
    float den = c0 / pz0 + c1 / pz1;
    float ps = fmaxf(num / den, 1e-8f);
    float ps2 = ps * ps;
    float ps4 = ps2 * ps2;
    float pstar = ps4 * ps;          // ps^5 exact (1/z == 5)
    bool vac = dv >= 3.0f * (c0 + c1);   // 2/(gamma-1) = 3
    bool dsb = pstar > fmaxf(q0, q1);
    bool drb = pstar < fminf(q0, q1);
    int label = vac ? 3 : (drb ? 1 : (dsb ? 0 : 2));

    // ---- features (flipped), packed as {x,x} for f32x2 FMA
    float ft[20];
    ft[0] = P0.x;  ft[1] = P0.y;  ft[2] = P1.x;  ft[3] = P1.y;
    ft[4] = P2.x;  ft[5] = P2.y;
    ft[6] = U0.x;  ft[7] = U0.y;  ft[8] = U1.x;  ft[9] = U1.y;
    ft[10] = U2.x; ft[11] = U2.y;
    ft[12] = F0.x; ft[13] = F0.y; ft[14] = F1.x; ft[15] = F1.y;
    ft[16] = F2.x; ft[17] = F2.y;
    ft[18] = cx;   ft[19] = cn;
    u64 xx[20];
#pragma unroll
    for (int i = 0; i < 20; i++) xx[i] = pack2(ft[i], ft[i]);

    // ---- selected MLP (label 3 -> run with weights 0, zero afterwards)
    int wl = (label < 3) ? label : 0;
    const float* WB = sh + wl * MLP_STRIDE;
    float o0 = WB[1600], o1 = WB[1601], o2 = WB[1602];

#pragma unroll 4
    for (int j = 0; j < 64; j += 2) {
        u64 acc = *reinterpret_cast<const u64*>(WB + 1280 + j);  // {b1[j], b1[j+1]}
#pragma unroll
        for (int i = 0; i < 20; i++) {
            u64 w = *reinterpret_cast<const u64*>(WB + i * 64 + j);
            acc = fma2(xx[i], w, acc);
        }
        float h0, h1;
        unpack2(acc, h0, h1);
        float t0 = fast_tanh(h0);
        float t1 = fast_tanh(h1);
        float4 w2a = *reinterpret_cast<const float4*>(WB + 1344 + j * 4);
        float4 w2b = *reinterpret_cast<const float4*>(WB + 1344 + (j + 1) * 4);
        o0 = fmaf(t0, w2a.x, o0);
        o1 = fmaf(t0, w2a.y, o1);
        o2 = fmaf(t0, w2a.z, o2);
        o0 = fmaf(t1, w2b.x, o0);
        o1 = fmaf(t1, w2b.y, o1);
        o2 = fmaf(t1, w2b.z, o2);
    }

    // ---- selection chain: vacuum -> 0 ; cont -> HLLE ; flip -> *(-1,-1,1)
    if (label == 3) { o0 = 0.0f; o1 = 0.0f; o2 = 0.0f; }
    if (cont)       { o0 = hl0;  o1 = hl1;  o2 = hl2; }
    if (flip)       { o0 = -o0;  o1 = -o1; }

    float* op = out + (size_t)n * 3;
    op[0] = o0;
    op[1] = o1;
    op[2] = o2;
}

extern "C" void kernel_launch(void* const* d_in, const int* in_sizes, int n_in,
                              void* d_out, int out_size) {
    const float* P    = (const float*)d_in[0];
    const float* U    = (const float*)d_in[1];
    const float* F    = (const float*)d_in[2];
    const float* cmax = (const float*)d_in[3];
    const float* cmin = (const float*)d_in[4];
    const float* W1_ds = (const float*)d_in[5];
    const float* b1_ds = (const float*)d_in[6];
    const float* W2_ds = (const float*)d_in[7];
    const float* b2_ds = (const float*)d_in[8];
    const float* W1_dr = (const float*)d_in[9];
    const float* b1_dr = (const float*)d_in[10];
    const float* W2_dr = (const float*)d_in[11];
    const float* b2_dr = (const float*)d_in[12];
    const float* W1_rs = (const float*)d_in[13];
    const float* b1_rs = (const float*)d_in[14];
    const float* W2_rs = (const float*)d_in[15];
    const float* b2_rs = (const float*)d_in[16];

    int N = in_sizes[3];  // cmax element count = number of cells
    float* out = (float*)d_out;

    int blocks = (N + NTH - 1) / NTH;
    riemann_kernel<<<blocks, NTH>>>(
        P, U, F, cmax, cmin,
        W1_ds, b1_ds, W2_ds, b2_ds,
        W1_dr, b1_dr, W2_dr, b2_dr,
        W1_rs, b1_rs, W2_rs, b2_rs,
        out, N);
}

// round 3
// speedup vs baseline: 1.5148x; 1.5148x over previous
#include <cuda_runtime.h>

// RiemannSolver, round 2: label-compaction + 2-cells-per-thread MLP.
//
// Kernel 1: classify each cell (flip/cont/wave-pattern) -> route in {0:ds,
//   1:dr, 2:rs, 3:vacuum, 4:HLLE}; scatter cell indices into 5 buckets
//   (block-aggregated atomics).
// Kernel 2: walk compacted order. Warps are route-uniform -> all weight LDS
//   broadcast. Each thread handles 2 same-route cells, sharing every weight
//   load: W1 via LDS.128 (ulonglong2 -> two u64 f32x2 weight pairs, no MOV
//   packing), features pre-packed {x,x}, fma.rn.f32x2 accumulators.

typedef unsigned long long u64;

#define NTH 256
#define NC 1048576
#define GAMMA_F 1.6666666666666667f
// per-MLP shared layout: W1[20*64]=1280 | b1[64] | W2 padded [64*4]=256 | b2[4]
#define MLP_STRIDE 1604
#define SH_TOTAL (3 * MLP_STRIDE)

__device__ int g_cnt[8];
__device__ int g_bucket[5 * NC];

__device__ __forceinline__ u64 pack2(float lo, float hi) {
    u64 r;
    asm("mov.b64 %0, {%1, %2};" : "=l"(r) : "f"(lo), "f"(hi));
    return r;
}
__device__ __forceinline__ void unpack2(u64 v, float& lo, float& hi) {
    asm("mov.b64 {%0, %1}, %2;" : "=f"(lo), "=f"(hi) : "l"(v));
}
__device__ __forceinline__ u64 fma2(u64 a, u64 b, u64 c) {
    u64 d;
    asm("fma.rn.f32x2 %0, %1, %2, %3;" : "=l"(d) : "l"(a), "l"(b), "l"(c));
    return d;
}

// tanh(x) = 1 - 2/(e^{2x}+1), valid for all x (saturates correctly at +-inf).
// FMUL + MUFU.EX2 + FADD + MUFU.RCP + FFMA = 5 ops.
__device__ __forceinline__ float tanh_fast(float x) {
    float p = 2.885390081777927f * x;   // 2x * log2(e)
    float e;
    asm("ex2.approx.f32 %0, %1;" : "=f"(e) : "f"(p));
    float s = e + 1.0f;
    float r;
    asm("rcp.approx.f32 %0, %1;" : "=f"(r) : "f"(s));
    return fmaf(-2.0f, r, 1.0f);
}

// ---------------------------------------------------------------------------
__global__ void k_zero() {
    if (threadIdx.x < 8) g_cnt[threadIdx.x] = 0;
}

// ---------------------------------------------------------------------------
__global__ __launch_bounds__(NTH)
void k_classify(const float* __restrict__ P, int N) {
    __shared__ int shCnt[5];
    __shared__ int shBase[5];
    __shared__ int wBase[NTH / 32][5];
    int tid = threadIdx.x;
    if (tid < 5) shCnt[tid] = 0;
    __syncthreads();

    int n = blockIdx.x * NTH + tid;
    int route = 5;
    if (n < N) {
        const float2* Pp = reinterpret_cast<const float2*>(P) + (size_t)n * 3;
        float2 P0 = Pp[0], P1 = Pp[1], P2 = Pp[2];
        bool flip = P1.y > P1.x;
        if (flip) {
            float t;
            t = P0.x; P0.x = P0.y; P0.y = t;
            t = P1.x; P1.x = P1.y; P1.y = t;
            t = P2.x; P2.x = -P2.y; P2.y = -t;
        }
        float d0 = fabsf(P0.y - P0.x);
        float d1 = fabsf(P1.y - P1.x);
        float d2 = fabsf(P2.y - P2.x);
        bool cont = fmaxf(d0, fmaxf(d1, d2)) < 0.005f;

        float r0 = P0.x, r1 = P0.y;
        float q0 = P1.x, q1 = P1.y;
        float v0 = P2.x, v1 = P2.y;
        float c0 = sqrtf(GAMMA_F * q0 / r0);
        float c1 = sqrtf(GAMMA_F * q1 / r1);
        float dv = v1 - v0;
        float num = c0 + c1 - 0.33333334f * dv;
        float pz0 = exp2f(0.2f * __log2f(q0));
        float pz1 = exp2f(0.2f * __log2f(q1));
        float den = c0 / pz0 + c1 / pz1;
        float ps = fmaxf(num / den, 1e-8f);
        float ps2 = ps * ps;
        float ps4 = ps2 * ps2;
        float pstar = ps4 * ps;
        bool vac = dv >= 3.0f * (c0 + c1);
        bool dsb = pstar > fmaxf(q0, q1);
        bool drb = pstar < fminf(q0, q1);
        int label = vac ? 3 : (drb ? 1 : (dsb ? 0 : 2));
        route = cont ? 4 : label;
    }

    int lane = tid & 31, w = tid >> 5;
    int myrank = 0;
#pragma unroll
    for (int r = 0; r < 5; r++) {
        unsigned bal = __ballot_sync(0xffffffffu, route == r);
        if (route == r) myrank = __popc(bal & ((1u << lane) - 1u));
        if (lane == 0 && bal) wBase[w][r] = atomicAdd(&shCnt[r], __popc(bal));
    }
    __syncthreads();
    if (tid < 5) shBase[tid] = atomicAdd(&g_cnt[tid], shCnt[tid]);
    __syncthreads();
    if (route < 5) {
        int pos = shBase[route] + wBase[w][route] + myrank;
        g_bucket[route * NC + pos] = n;
    }
}

// ---------------------------------------------------------------------------
// Load cell n, apply flip normalization, emit 20 features packed {x,x}.
__device__ __forceinline__ void prep_cell(
    int n, const float* __restrict__ P, const float* __restrict__ U,
    const float* __restrict__ F, const float* __restrict__ cmax,
    const float* __restrict__ cmin, u64* xx, bool& flip,
    float2* Uo, float2* Fo, float& cxo, float& cno)
{
    const float2* Pp = reinterpret_cast<const float2*>(P) + (size_t)n * 3;
    const float2* Up = reinterpret_cast<const float2*>(U) + (size_t)n * 3;
    const float2* Fp = reinterpret_cast<const float2*>(F) + (size_t)n * 3;
    float2 P0 = Pp[0], P1 = Pp[1], P2 = Pp[2];
    float2 U0 = Up[0], U1 = Up[1], U2 = Up[2];
    float2 F0 = Fp[0], F1 = Fp[1], F2 = Fp[2];
    float cx = cmax[n];
    float cn = cmin[n];

    flip = P1.y > P1.x;
    if (flip) {
        float t;
        t = P0.x; P0.x = P0.y; P0.y = t;
        t = P1.x; P1.x = P1.y; P1.y = t;
        t = P2.x; P2.x = -P2.y; P2.y = -t;
        t = U0.x; U0.x = U0.y; U0.y = t;
        t = U1.x; U1.x = U1.y; U1.y = t;
        t = U2.x; U2.x = -U2.y; U2.y = -t;
        t = F0.x; F0.x = -F0.y; F0.y = -t;
        t = F1.x; F1.x = -F1.y; F1.y = -t;
        t = F2.x; F2.x = F2.y;  F2.y = t;
    }
    xx[0]  = pack2(P0.x, P0.x);  xx[1]  = pack2(P0.y, P0.y);
    xx[2]  = pack2(P1.x, P1.x);  xx[3]  = pack2(P1.y, P1.y);
    xx[4]  = pack2(P2.x, P2.x);  xx[5]  = pack2(P2.y, P2.y);
    xx[6]  = pack2(U0.x, U0.x);  xx[7]  = pack2(U0.y, U0.y);
    xx[8]  = pack2(U1.x, U1.x);  xx[9]  = pack2(U1.y, U1.y);
    xx[10] = pack2(U2.x, U2.x);  xx[11] = pack2(U2.y, U2.y);
    xx[12] = pack2(F0.x, F0.x);  xx[13] = pack2(F0.y, F0.y);
    xx[14] = pack2(F1.x, F1.x);  xx[15] = pack2(F1.y, F1.y);
    xx[16] = pack2(F2.x, F2.x);  xx[17] = pack2(F2.y, F2.y);
    xx[18] = pack2(cx, cx);      xx[19] = pack2(cn, cn);
    Uo[0] = U0; Uo[1] = U1; Uo[2] = U2;
    Fo[0] = F0; Fo[1] = F1; Fo[2] = F2;
    cxo = cx; cno = cn;
}

// Slow path: one cell, any route. FP op order matches the fast path exactly
// (so pairing nondeterminism never changes results).
__device__ __noinline__ void process_one(
    int cell, int route, const float* __restrict__ sh,
    const float* __restrict__ P, const float* __restrict__ U,
    const float* __restrict__ F, const float* __restrict__ cmax,
    const float* __restrict__ cmin, float* __restrict__ out)
{
    float* op = out + (size_t)cell * 3;
    if (route == 3) {            // vacuum -> 0 (sign flip irrelevant)
        op[0] = 0.0f; op[1] = 0.0f; op[2] = 0.0f;
        return;
    }
    u64 xx[20];
    bool flip;
    float2 Uv[3], Fv[3];
    float cx, cn;
    prep_cell(cell, P, U, F, cmax, cmin, xx, flip, Uv, Fv, cx, cn);

    if (route == 4) {            // HLLE
        float inv = 1.0f / (cx - cn);
        float cc = cx * cn;
        float o0 = (cx * Fv[0].x - cn * Fv[0].y + cc * (Uv[0].y - Uv[0].x)) * inv;
        float o1 = (cx * Fv[1].x - cn * Fv[1].y + cc * (Uv[1].y - Uv[1].x)) * inv;
        float o2 = (cx * Fv[2].x - cn * Fv[2].y + cc * (Uv[2].y - Uv[2].x)) * inv;
        if (flip) { o0 = -o0; o1 = -o1; }
        op[0] = o0; op[1] = o1; op[2] = o2;
        return;
    }

    const float* WB = sh + route * MLP_STRIDE;
    float o0 = WB[1600], o1 = WB[1601], o2 = WB[1602];
#pragma unroll 1
    for (int jg = 0; jg < 16; jg++) {
        const float* base = WB + jg * 4;
        ulonglong2 bb = *reinterpret_cast<const ulonglong2*>(WB + 1280 + jg * 4);
        u64 a01 = bb.x, a23 = bb.y;
#pragma unroll
        for (int i = 0; i < 20; i++) {
            ulonglong2 w = *reinterpret_cast<const ulonglong2*>(base + i * 64);
            a01 = fma2(xx[i], w.x, a01);
            a23 = fma2(xx[i], w.y, a23);
        }
        float h[4];
        unpack2(a01, h[0], h[1]);
        unpack2(a23, h[2], h[3]);
#pragma unroll
        for (int k = 0; k < 4; k++) {
            float4 w2 = *reinterpret_cast<const float4*>(WB + 1344 + (jg * 4 + k) * 4);
            float t = tanh_fast(h[k]);
            o0 = fmaf(t, w2.x, o0);
            o1 = fmaf(t, w2.y, o1);
            o2 = fmaf(t, w2.z, o2);
        }
    }
    if (flip) { o0 = -o0; o1 = -o1; }
    op[0] = o0; op[1] = o1; op[2] = o2;
}

// ---------------------------------------------------------------------------
__global__ __launch_bounds__(NTH)
void k_mlp(
    const float* __restrict__ P, const float* __restrict__ U,
    const float* __restrict__ F,
    const float* __restrict__ cmax, const float* __restrict__ cmin,
    const float* __restrict__ W1_0, const float* __restrict__ b1_0,
    const float* __restrict__ W2_0, const float* __restrict__ b2_0,
    const float* __restrict__ W1_1, const float* __restrict__ b1_1,
    const float* __restrict__ W2_1, const float* __restrict__ b2_1,
    const float* __restrict__ W1_2, const float* __restrict__ b1_2,
    const float* __restrict__ W2_2, const float* __restrict__ b2_2,
    float* __restrict__ out, int N)
{
    __shared__ __align__(16) float sh[SH_TOTAL];

    for (int idx = threadIdx.x; idx < SH_TOTAL; idx += NTH) {
        int m = idx / MLP_STRIDE;
        int r = idx - m * MLP_STRIDE;
        const float* W1 = (m == 0) ? W1_0 : (m == 1) ? W1_1 : W1_2;
        const float* b1 = (m == 0) ? b1_0 : (m == 1) ? b1_1 : b1_2;
        const float* W2 = (m == 0) ? W2_0 : (m == 1) ? W2_1 : W2_2;
        const float* b2 = (m == 0) ? b2_0 : (m == 1) ? b2_1 : b2_2;
        float v;
        if (r < 1280) {
            v = W1[r];
        } else if (r < 1344) {
            v = b1[r - 1280];
        } else if (r < 1600) {
            int q = r - 1344;
            int j = q >> 2, k = q & 3;
            v = (k < 3) ? W2[j * 3 + k] : 0.0f;
        } else {
            int k = r - 1600;
            v = (k < 3) ? b2[k] : 0.0f;
        }
        sh[idx] = v;
    }
    __syncthreads();

    int t = blockIdx.x * NTH + threadIdx.x;
    int v0 = 2 * t, v1 = 2 * t + 1;
    if (v0 >= N) return;

    int c0 = g_cnt[0], c1 = g_cnt[1], c2 = g_cnt[2], c3 = g_cnt[3];
    int e0 = c0, e1 = e0 + c1, e2 = e1 + c2, e3 = e2 + c3;

    int r0, cell0, r1 = -1, cell1 = -1;
    {
        int base;
        if (v0 < e0)      { r0 = 0; base = 0; }
        else if (v0 < e1) { r0 = 1; base = e0; }
        else if (v0 < e2) { r0 = 2; base = e1; }
        else if (v0 < e3) { r0 = 3; base = e2; }
        else              { r0 = 4; base = e3; }
        cell0 = g_bucket[r0 * NC + (v0 - base)];
    }
    bool have1 = (v1 < N);
    if (have1) {
        int base;
        if (v1 < e0)      { r1 = 0; base = 0; }
        else if (v1 < e1) { r1 = 1; base = e0; }
        else if (v1 < e2) { r1 = 2; base = e1; }
        else if (v1 < e3) { r1 = 3; base = e2; }
        else              { r1 = 4; base = e3; }
        cell1 = g_bucket[r1 * NC + (v1 - base)];
    }

    if (have1 && r0 == r1 && r0 < 3) {
        // ---- fast path: two same-label MLP cells sharing every weight load
        u64 x0[20], x1[20];
        bool f0, f1;
        float2 Uv[3], Fv[3];
        float cxa, cna;
        prep_cell(cell0, P, U, F, cmax, cmin, x0, f0, Uv, Fv, cxa, cna);
        prep_cell(cell1, P, U, F, cmax, cmin, x1, f1, Uv, Fv, cxa, cna);

        const float* WB = sh + r0 * MLP_STRIDE;
        float o00 = WB[1600], o01 = WB[1601], o02 = WB[1602];
        float o10 = o00, o11 = o01, o12 = o02;

#pragma unroll 1
        for (int jg = 0; jg < 16; jg++) {
            const float* base = WB + jg * 4;
            ulonglong2 bb = *reinterpret_cast<const ulonglong2*>(WB + 1280 + jg * 4);
            u64 a001 = bb.x, a023 = bb.y;
            u64 a101 = bb.x, a123 = bb.y;
#pragma unroll
            for (int i = 0; i < 20; i++) {
                ulonglong2 w = *reinterpret_cast<const ulonglong2*>(base + i * 64);
                a001 = fma2(x0[i], w.x, a001);
                a023 = fma2(x0[i], w.y, a023);
                a101 = fma2(x1[i], w.x, a101);
                a123 = fma2(x1[i], w.y, a123);
            }
            float h0[4], h1[4];
            unpack2(a001, h0[0], h0[1]);
            unpack2(a023, h0[2], h0[3]);
            unpack2(a101, h1[0], h1[1]);
            unpack2(a123, h1[2], h1[3]);
#pragma unroll
            for (int k = 0; k < 4; k++) {
                float4 w2 = *reinterpret_cast<const float4*>(WB + 1344 + (jg * 4 + k) * 4);
                float ta = tanh_fast(h0[k]);
                float tb = tanh_fast(h1[k]);
                o00 = fmaf(ta, w2.x, o00);
                o01 = fmaf(ta, w2.y, o01);
                o02 = fmaf(ta, w2.z, o02);
                o10 = fmaf(tb, w2.x, o10);
                o11 = fmaf(tb, w2.y, o11);
                o12 = fmaf(tb, w2.z, o12);
            }
        }
        if (f0) { o00 = -o00; o01 = -o01; }
        if (f1) { o10 = -o10; o11 = -o11; }
        float* p0 = out + (size_t)cell0 * 3;
        float* p1 = out + (size_t)cell1 * 3;
        p0[0] = o00; p0[1] = o01; p0[2] = o02;
        p1[0] = o10; p1[1] = o11; p1[2] = o12;
    } else {
        process_one(cell0, r0, sh, P, U, F, cmax, cmin, out);
        if (have1) process_one(cell1, r1, sh, P, U, F, cmax, cmin, out);
    }
}

// ---------------------------------------------------------------------------
extern "C" void kernel_launch(void* const* d_in, const int* in_sizes, int n_in,
                              void* d_out, int out_size) {
    const float* P    = (const float*)d_in[0];
    const float* U    = (const float*)d_in[1];
    const float* F    = (const float*)d_in[2];
    const float* cmax = (const float*)d_in[3];
    const float* cmin = (const float*)d_in[4];
    const float* W1_ds = (const float*)d_in[5];
    const float* b1_ds = (const float*)d_in[6];
    const float* W2_ds = (const float*)d_in[7];
    const float* b2_ds = (const float*)d_in[8];
    const float* W1_dr = (const float*)d_in[9];
    const float* b1_dr = (const float*)d_in[10];
    const float* W2_dr = (const float*)d_in[11];
    const float* b2_dr = (const float*)d_in[12];
    const float* W1_rs = (const float*)d_in[13];
    const float* b1_rs = (const float*)d_in[14];
    const float* W2_rs = (const float*)d_in[15];
    const float* b2_rs = (const float*)d_in[16];

    int N = in_sizes[3];
    float* out = (float*)d_out;

    k_zero<<<1, 32>>>();
    k_classify<<<(N + NTH - 1) / NTH, NTH>>>(P, N);
    int nt2 = (N + 1) / 2;
    k_mlp<<<(nt2 + NTH - 1) / NTH, NTH>>>(
        P, U, F, cmax, cmin,
        W1_ds, b1_ds, W2_ds, b2_ds,
        W1_dr, b1_dr, W2_dr, b2_dr,
        W1_rs, b1_rs, W2_rs, b2_rs,
        out, N);
}